// round 1
// baseline (speedup 1.0000x reference)
#include <cuda_runtime.h>

// Stacked spectral filter, exploiting diagonal Lambda:
//   y = U^T x                         (GEMM1)
//   w[j,:] = g(lam_j) * y[j,:]        (fused epilogue of GEMM1)
//   out = alpha*x + U w               (GEMM2)
// g(l) = sum_i 4*c_i/(a_i-b_i)^2 * relu((a_i-l)(l-b_i))

#define BM 64
#define BN 64
#define BK 16
#define BMP 68   // padded BM for transposed A tile in GEMM2 (16B-aligned rows)

// scratch for w = g * (U^T x)   [N, F] = [2048, 256]
__device__ float g_w[2048 * 256];

// ---------------------------------------------------------------------------
// GEMM1: W[j,f] = g(lam_j) * sum_k U[k,j] * X[k,f]
// A-tile = U[k, j]  (j contiguous -> coalesced, stored as As[k][j] directly)
// ---------------------------------------------------------------------------
__global__ __launch_bounds__(256, 2)
void k1_utx_scale(const float* __restrict__ U, const float* __restrict__ X,
                  const float* __restrict__ lam,
                  const float* __restrict__ a, const float* __restrict__ b,
                  const float* __restrict__ c, int nfilt,
                  int N, int F)
{
    __shared__ __align__(16) float As[2][BK][BM];
    __shared__ __align__(16) float Bs[2][BK][BN];

    const int tid = threadIdx.x;
    const int tx = tid & 15;        // 0..15 -> 4 cols each
    const int ty = tid >> 4;        // 0..15 -> 4 rows each
    const int m0 = blockIdx.x * BM; // j
    const int n0 = blockIdx.y * BN; // f

    const int lk = tid >> 4;         // 0..15  (k within tile)
    const int lc = (tid & 15) << 2;  // 0..60  (col within tile, float4)

    float acc[4][4] = {};

    // preload tile 0
    {
        float4 av = *(const float4*)(U + (size_t)lk * N + m0 + lc);
        float4 bv = *(const float4*)(X + (size_t)lk * F + n0 + lc);
        *(float4*)&As[0][lk][lc] = av;
        *(float4*)&Bs[0][lk][lc] = bv;
    }
    __syncthreads();

    const int nk = N / BK;
    for (int t = 0; t < nk; ++t) {
        const int cur = t & 1;
        float4 av, bv;
        const bool more = (t + 1 < nk);
        if (more) {
            const int k0 = (t + 1) * BK;
            av = *(const float4*)(U + (size_t)(k0 + lk) * N + m0 + lc);
            bv = *(const float4*)(X + (size_t)(k0 + lk) * F + n0 + lc);
        }
#pragma unroll
        for (int kk = 0; kk < BK; ++kk) {
            float4 a4 = *(const float4*)&As[cur][kk][ty << 2];
            float4 b4 = *(const float4*)&Bs[cur][kk][tx << 2];
            float ar[4] = {a4.x, a4.y, a4.z, a4.w};
            float br[4] = {b4.x, b4.y, b4.z, b4.w};
#pragma unroll
            for (int i = 0; i < 4; ++i)
#pragma unroll
                for (int j = 0; j < 4; ++j)
                    acc[i][j] += ar[i] * br[j];
        }
        if (more) {
            *(float4*)&As[cur ^ 1][lk][lc] = av;
            *(float4*)&Bs[cur ^ 1][lk][lc] = bv;
        }
        __syncthreads();
    }

    // epilogue: scale each row by g(lam_row)
#pragma unroll
    for (int i = 0; i < 4; ++i) {
        const int row = m0 + (ty << 2) + i;
        const float lv = lam[(size_t)row * N + row];
        float g = 0.f;
#pragma unroll 4
        for (int tf = 0; tf < nfilt; ++tf) {
            const float at = a[tf], bt = b[tf];
            float d = (at - lv) * (lv - bt);
            d = d > 0.f ? d : 0.f;
            const float ab = at - bt;
            g += (4.f * c[tf] / (ab * ab)) * d;
        }
        float* wrow = g_w + (size_t)row * F + n0 + (tx << 2);
#pragma unroll
        for (int j = 0; j < 4; ++j)
            wrow[j] = g * acc[i][j];
    }
}

// ---------------------------------------------------------------------------
// GEMM2: out[n,f] = alpha * X[n,f] + sum_j U[n,j] * W[j,f]
// A-tile = U[n, j] (j contiguous) stored transposed As[j][n] for the k-loop
// ---------------------------------------------------------------------------
__global__ __launch_bounds__(256, 2)
void k2_uw(const float* __restrict__ U, const float* __restrict__ X,
           const float* __restrict__ alpha,
           float* __restrict__ out, int N, int F)
{
    __shared__ __align__(16) float As[2][BK][BMP];
    __shared__ __align__(16) float Bs[2][BK][BN];

    const int tid = threadIdx.x;
    const int tx = tid & 15;
    const int ty = tid >> 4;
    const int m0 = blockIdx.x * BM; // n (output row)
    const int n0 = blockIdx.y * BN; // f

    // A loader: 64 rows x 16 cols, one float4 per thread, transposed store
    const int ar = tid >> 2;          // 0..63  row within tile
    const int ac = (tid & 3) << 2;    // 0,4,8,12  k within tile

    // B loader (same as kernel 1)
    const int lk = tid >> 4;
    const int lc = (tid & 15) << 2;

    float acc[4][4] = {};

    {
        float4 uv = *(const float4*)(U + (size_t)(m0 + ar) * N + ac);
        As[0][ac + 0][ar] = uv.x;
        As[0][ac + 1][ar] = uv.y;
        As[0][ac + 2][ar] = uv.z;
        As[0][ac + 3][ar] = uv.w;
        float4 bv = *(const float4*)(g_w + (size_t)lk * F + n0 + lc);
        *(float4*)&Bs[0][lk][lc] = bv;
    }
    __syncthreads();

    const int nk = N / BK;
    for (int t = 0; t < nk; ++t) {
        const int cur = t & 1;
        float4 uv, bv;
        const bool more = (t + 1 < nk);
        if (more) {
            const int k0 = (t + 1) * BK;
            uv = *(const float4*)(U + (size_t)(m0 + ar) * N + k0 + ac);
            bv = *(const float4*)(g_w + (size_t)(k0 + lk) * F + n0 + lc);
        }
#pragma unroll
        for (int kk = 0; kk < BK; ++kk) {
            float4 a4 = *(const float4*)&As[cur][kk][ty << 2];
            float4 b4 = *(const float4*)&Bs[cur][kk][tx << 2];
            float ar4[4] = {a4.x, a4.y, a4.z, a4.w};
            float br4[4] = {b4.x, b4.y, b4.z, b4.w};
#pragma unroll
            for (int i = 0; i < 4; ++i)
#pragma unroll
                for (int j = 0; j < 4; ++j)
                    acc[i][j] += ar4[i] * br4[j];
        }
        if (more) {
            As[cur ^ 1][ac + 0][ar] = uv.x;
            As[cur ^ 1][ac + 1][ar] = uv.y;
            As[cur ^ 1][ac + 2][ar] = uv.z;
            As[cur ^ 1][ac + 3][ar] = uv.w;
            *(float4*)&Bs[cur ^ 1][lk][lc] = bv;
        }
        __syncthreads();
    }

    const float al = alpha[0];
#pragma unroll
    for (int i = 0; i < 4; ++i) {
        const int row = m0 + (ty << 2) + i;
        const float* xrow = X + (size_t)row * F + n0 + (tx << 2);
        float* orow = out + (size_t)row * F + n0 + (tx << 2);
#pragma unroll
        for (int j = 0; j < 4; ++j)
            orow[j] = al * xrow[j] + acc[i][j];
    }
}

// ---------------------------------------------------------------------------
extern "C" void kernel_launch(void* const* d_in, const int* in_sizes, int n_in,
                              void* d_out, int out_size)
{
    const float* X     = (const float*)d_in[0];  // [N,F]
    const float* Lam   = (const float*)d_in[1];  // [N,N] (diagonal in practice)
    const float* U     = (const float*)d_in[2];  // [N,N]
    const float* a     = (const float*)d_in[3];  // [K]
    const float* b     = (const float*)d_in[4];  // [K]
    const float* c     = (const float*)d_in[5];  // [K]
    const float* alpha = (const float*)d_in[6];  // [1]
    // d_in[7] = edge_index: unused by the reference

    const int nfilt = in_sizes[3];
    // N from lam element count (N*N), F from x element count (N*F)
    int N = 1;
    {
        long s = in_sizes[1];
        long lo = 1, hi = 65536;
        while (lo < hi) { long mid = (lo + hi) >> 1; if (mid * mid < s) lo = mid + 1; else hi = mid; }
        N = (int)lo;
    }
    const int F = in_sizes[0] / N;

    dim3 blk(256);
    dim3 grid(N / BM, F / BN);

    k1_utx_scale<<<grid, blk>>>(U, X, Lam, a, b, c, nfilt, N, F);
    k2_uw<<<grid, blk>>>(U, X, alpha, (float*)d_out, N, F);
}